// round 15
// baseline (speedup 1.0000x reference)
#include <cuda_runtime.h>

#define NP 200000
#define KN 16
#define MR 3200000
#define H1C 16
#define H2C 32
#define CC 64
#define HD 256
#define BNEPS 1e-5

// ---------------- scratch (no allocations allowed) ----------------
__device__ double g_MX[7],  g_MXX[28];    // sum x, sum x x^T (triangle)
__device__ double g_MH[16], g_MHH[136];   // sum h1, sum h1 h1^T (triangle)
__device__ double g_S3[CC], g_Q3[CC];
__device__ float  g_par1[2*H1C];
__device__ float  g_par2[2*H2C];
__device__ float4 g_xc4[2*MR];            // cached gathered rows (8 floats/row), 102.4MB
__device__ float  g_pooled[NP*CC];        // 51.2MB
__device__ float  g_Weff[CC*HD];
__device__ float  g_bias[HD];

typedef unsigned long long u64;

// ---------------- packed f32x2 helpers ----------------
__device__ __forceinline__ u64 pk2(float lo, float hi){
    u64 r; asm("mov.b64 %0, {%1, %2};" : "=l"(r) : "f"(lo), "f"(hi)); return r;
}
__device__ __forceinline__ u64 pkc(float c){ return pk2(c, c); }
__device__ __forceinline__ void up2(u64 v, float &lo, float &hi){
    asm("mov.b64 {%0, %1}, %2;" : "=f"(lo), "=f"(hi) : "l"(v));
}
__device__ __forceinline__ u64 f2fma(u64 a, u64 b, u64 c){
    u64 r; asm("fma.rn.f32x2 %0, %1, %2, %3;" : "=l"(r) : "l"(a), "l"(b), "l"(c)); return r;
}
__device__ __forceinline__ u64 f2mul(u64 a, u64 b){
    u64 r; asm("mul.rn.f32x2 %0, %1, %2;" : "=l"(r) : "l"(a), "l"(b)); return r;
}
__device__ __forceinline__ float ex2a(float x){ float r; asm("ex2.approx.f32 %0, %1;" : "=f"(r) : "f"(x)); return r; }
__device__ __forceinline__ float rcpa(float x){ float r; asm("rcp.approx.f32 %0, %1;" : "=f"(r) : "f"(x)); return r; }

// Packed exact-GELU on two floats (A&S 7.1.26 erf, |err| ~1e-6 abs):
//   s = v/sqrt(2); erf(|s|) = 1 - P(t)*exp(-s^2), t = 1/(1+0.3275911|s|)
//   gelu(v) = v * (0.5 + 0.5*sign(v)*(1 - P*e))
__device__ __forceinline__ u64 gelu2(u64 v){
    u64 s  = f2mul(v, pkc(0.70710678118654752f));
    u64 s2 = f2mul(s, s);
    u64 ne = f2mul(s2, pkc(-1.4426950408889634f));
    float n0, n1; up2(ne, n0, n1);
    u64 e  = pk2(ex2a(n0), ex2a(n1));
    u64 as = s & 0x7fffffff7fffffffull;
    u64 d  = f2fma(as, pkc(0.3275911f), pkc(1.0f));
    float d0, d1; up2(d, d0, d1);
    u64 t  = pk2(rcpa(d0), rcpa(d1));
    u64 P  = pkc(1.061405429f);
    P = f2fma(P, t, pkc(-1.453152027f));
    P = f2fma(P, t, pkc(1.421413741f));
    P = f2fma(P, t, pkc(-0.284496736f));
    P = f2fma(P, t, pkc(0.254829592f));
    P = f2mul(P, t);
    u64 y   = f2mul(P, e);
    u64 omy = f2fma(y, pkc(-1.0f), pkc(1.0f));       // 1 - y  (>= 0)
    u64 g   = omy ^ (v & 0x8000000080000000ull);     // sign(v)*(1-y)
    u64 h   = f2fma(g, pkc(0.5f), pkc(0.5f));
    return f2mul(v, h);
}

// acc = x @ w1 (packed output; w1 shared, row-major [7][16])
__device__ __forceinline__ void lin1p(const float x[7], const float* sw1, u64 acc[8]){
    #pragma unroll
    for(int u=0;u<8;u++) acc[u]=0ull;
    #pragma unroll
    for(int i=0;i<7;i++){
        u64 xp = pk2(x[i], x[i]);
        const u64* w = reinterpret_cast<const u64*>(sw1 + i*H1C);
        #pragma unroll
        for(int u=0;u<8;u++) acc[u] = f2fma(xp, w[u], acc[u]);
    }
}

// acc = h @ w2 (packed output; w2 shared, row-major [16][32])
__device__ __forceinline__ void lin2p(const float h[H1C], const float* sw2, u64 acc[16]){
    #pragma unroll
    for(int u=0;u<16;u++) acc[u]=0ull;
    #pragma unroll
    for(int i=0;i<H1C;i++){
        u64 hp = pk2(h[i], h[i]);
        const u64* w = reinterpret_cast<const u64*>(sw2 + i*H2C);
        #pragma unroll
        for(int u=0;u<16;u++) acc[u] = f2fma(hp, w[u], acc[u]);
    }
}

__device__ __forceinline__ float wred(float v){
    #pragma unroll
    for(int o=16;o>0;o>>=1) v += __shfl_down_sync(0xffffffffu, v, o);
    return v;
}

__device__ __forceinline__ int tri7(int i, int k){
    if(i>k){int s=i;i=k;k=s;}
    return i*7 - (i*(i-1))/2 + (k-i);
}
__device__ __forceinline__ int tri16(int i, int k){
    if(i>k){int s=i;i=k;k=s;}
    return i*16 - (i*(i-1))/2 + (k-i);
}

// ---------------- kernels ----------------
__global__ void k_init(){
    int t = threadIdx.x;
    if(t<7)   g_MX[t]=0.0;
    if(t<28)  g_MXX[t]=0.0;
    if(t<16)  g_MH[t]=0.0;
    if(t<136) g_MHH[t]=0.0;
    if(t<CC){ g_S3[t]=0.0; g_Q3[t]=0.0; }
}

// ---- pass1: thread = one point. Center loaded once, 16 neighbors in two 8-wide
// independent gather groups, 512B contiguous store per thread.
__device__ __forceinline__ void p1_group8(const float* __restrict__ p,
    const float* __restrict__ f, int4 ga, int4 gb,
    float px, float py, float pz, int rbase, float* sx, float* sxx){
    int idx0=ga.x, idx1=ga.y, idx2=ga.z, idx3=ga.w;
    int idx4=gb.x, idx5=gb.y, idx6=gb.z, idx7=gb.w;
    float xb[8][7];
    #define GATH(j, id) { \
        xb[j][0]=p[3*(id)]-px; xb[j][1]=p[3*(id)+1]-py; xb[j][2]=p[3*(id)+2]-pz; \
        float4 fv = *reinterpret_cast<const float4*>(f + 4*(id)); \
        xb[j][3]=fv.x; xb[j][4]=fv.y; xb[j][5]=fv.z; xb[j][6]=fv.w; }
    GATH(0,idx0) GATH(1,idx1) GATH(2,idx2) GATH(3,idx3)
    GATH(4,idx4) GATH(5,idx5) GATH(6,idx6) GATH(7,idx7)
    #undef GATH
    #pragma unroll
    for(int j=0;j<8;j++){
        int c=0;
        #pragma unroll
        for(int i=0;i<7;i++){
            sx[i] += xb[j][i];
            #pragma unroll
            for(int k=i;k<7;k++) sxx[c++] += xb[j][i]*xb[j][k];
        }
        int r = rbase + j;
        float4 A; A.x=xb[j][0]; A.y=xb[j][1]; A.z=xb[j][2]; A.w=xb[j][3];
        float4 B; B.x=xb[j][4]; B.y=xb[j][5]; B.z=xb[j][6]; B.w=0.f;
        g_xc4[2*r]   = A;
        g_xc4[2*r+1] = B;
    }
}

__global__ void __launch_bounds__(256) k_pass1m(const float* __restrict__ p,
    const float* __restrict__ f, const int* __restrict__ gi){
    int n = blockIdx.x*blockDim.x + threadIdx.x;
    float sx[7], sxx[28];
    #pragma unroll
    for(int i=0;i<7;i++) sx[i]=0.f;
    #pragma unroll
    for(int i=0;i<28;i++) sxx[i]=0.f;

    if(n < NP){
        float px = p[3*n], py = p[3*n+1], pz = p[3*n+2];
        const int4* g4 = reinterpret_cast<const int4*>(gi + n*16);
        int4 ga = g4[0], gb = g4[1];
        p1_group8(p, f, ga, gb, px, py, pz, n*16,     sx, sxx);
        int4 gc = g4[2], gd = g4[3];
        p1_group8(p, f, gc, gd, px, py, pz, n*16 + 8, sx, sxx);
    }

    __shared__ float rs[7], rm[28];
    int tt = threadIdx.x;
    if(tt<7) rs[tt]=0.f;
    if(tt<28) rm[tt]=0.f;
    __syncthreads();
    int lane = tt & 31;
    #pragma unroll
    for(int i=0;i<7;i++){ float v=wred(sx[i]); if(lane==0) atomicAdd(&rs[i],v); }
    #pragma unroll
    for(int i=0;i<28;i++){ float v=wred(sxx[i]); if(lane==0) atomicAdd(&rm[i],v); }
    __syncthreads();
    if(tt<7)  atomicAdd(&g_MX[tt],  (double)rs[tt]);
    if(tt<28) atomicAdd(&g_MXX[tt], (double)rm[tt]);
}

__global__ void k_stats1(const float* __restrict__ w1, const float* __restrict__ g1,
                         const float* __restrict__ b1){
    int j = threadIdx.x;
    if(j >= H1C) return;
    double inv = 1.0/(double)MR;
    double m = 0.0, es = 0.0;
    for(int i=0;i<7;i++){
        double wij = (double)w1[i*H1C+j];
        m += g_MX[i]*inv*wij;
        for(int k=0;k<7;k++)
            es += g_MXX[tri7(i,k)]*inv * wij * (double)w1[k*H1C+j];
    }
    double v = es - m*m;
    double rs = rsqrt(v + BNEPS);
    float sc = (float)((double)g1[j] * rs);
    g_par1[j] = sc;
    g_par1[H1C+j] = b1[j] - (float)m * sc;
}

// ---- pass2: stream xc, h1 = gelu2(bn1(x@w1)) fully packed, lane-pair split
// triangle moments. 625 blocks x 256, 20 rows/thread exact.
__global__ void __launch_bounds__(256) k_pass2m(const float* __restrict__ w1){
    const int T = 625*256;
    __shared__ __align__(16) float sw1[7*H1C];
    __shared__ __align__(16) float sp1[2*H1C];
    int tt = threadIdx.x;
    if(tt < 7*H1C) sw1[tt]=w1[tt];
    if(tt < 2*H1C) sp1[tt]=g_par1[tt];
    __syncthreads();
    int lane = tt & 31;
    int par  = lane & 1;
    const u64* scp = reinterpret_cast<const u64*>(sp1);
    const u64* shp = reinterpret_cast<const u64*>(sp1 + H1C);

    float sh[16], mh[68];
    #pragma unroll
    for(int i=0;i<16;i++) sh[i]=0.f;
    #pragma unroll
    for(int i=0;i<68;i++) mh[i]=0.f;

    int t = blockIdx.x*blockDim.x + tt;
    int r = t;
    float4 A = g_xc4[2*r], B = g_xc4[2*r+1];
    #pragma unroll 1
    for(int it=0; it<20; it++){
        float x[7] = {A.x,A.y,A.z,A.w,B.x,B.y,B.z};
        int rn = r + T;
        if(it < 19){ A = g_xc4[2*rn]; B = g_xc4[2*rn+1]; }
        r = rn;
        u64 acc[8]; lin1p(x, sw1, acc);
        float h1[H1C];
        #pragma unroll
        for(int u=0;u<8;u++){
            u64 hv = gelu2(f2fma(acc[u], scp[u], shp[u]));
            up2(hv, h1[2*u], h1[2*u+1]);
        }
        float hp[H1C];
        #pragma unroll
        for(int j=0;j<H1C;j++) hp[j] = __shfl_xor_sync(0xffffffffu, h1[j], 1);
        #pragma unroll
        for(int j=0;j<H1C;j++) sh[j] += h1[j];
        // lane-pair split of the 136-entry triangle (row-pair sum is symmetric)
        if(par==0){
            int c=0;
            #pragma unroll
            for(int i=0;i<16;i++)
                #pragma unroll
                for(int k=i;k<16;k++){
                    if(c<68) mh[c] += h1[i]*h1[k] + hp[i]*hp[k];
                    c++;
                }
        } else {
            int c=0;
            #pragma unroll
            for(int i=0;i<16;i++)
                #pragma unroll
                for(int k=i;k<16;k++){
                    if(c>=68) mh[c-68] += h1[i]*h1[k] + hp[i]*hp[k];
                    c++;
                }
        }
    }
    __shared__ float rs[16], rm[136];
    if(tt<16) rs[tt]=0.f;
    if(tt<136) rm[tt]=0.f;
    __syncthreads();
    #pragma unroll
    for(int i=0;i<16;i++){ float v=wred(sh[i]); if(lane==0) atomicAdd(&rs[i],v); }
    #pragma unroll
    for(int e=0;e<68;e++){
        float v = mh[e];
        v += __shfl_down_sync(0xffffffffu, v, 16);
        v += __shfl_down_sync(0xffffffffu, v, 8);
        v += __shfl_down_sync(0xffffffffu, v, 4);
        v += __shfl_down_sync(0xffffffffu, v, 2);
        mh[e] = v;
    }
    if(lane==0){
        #pragma unroll
        for(int e=0;e<68;e++) atomicAdd(&rm[e], mh[e]);
    } else if(lane==1){
        #pragma unroll
        for(int e=0;e<68;e++) atomicAdd(&rm[68+e], mh[e]);
    }
    __syncthreads();
    if(tt<16)  atomicAdd(&g_MH[tt],  (double)rs[tt]);
    if(tt<136) atomicAdd(&g_MHH[tt], (double)rm[tt]);
}

__global__ void k_stats2(const float* __restrict__ w2, const float* __restrict__ g2,
                         const float* __restrict__ b2){
    int j = threadIdx.x;
    if(j >= H2C) return;
    double inv = 1.0/(double)MR;
    double m = 0.0, es = 0.0;
    for(int i=0;i<16;i++){
        double wij = (double)w2[i*H2C+j];
        m += g_MH[i]*inv*wij;
        for(int k=0;k<16;k++)
            es += g_MHH[tri16(i,k)]*inv * wij * (double)w2[k*H2C+j];
    }
    double v = es - m*m;
    double rs = rsqrt(v + BNEPS);
    float sc = (float)((double)g2[j] * rs);
    g_par2[j] = sc;
    g_par2[H2C+j] = b2[j] - (float)m * sc;
}

// ---- pass3: stream xc -> full MLP (packed gelu) -> a3 -> max over K -> pooled
// + fused stats. h2 transposed in smem; stage B q-outer with w3 loaded once per q.
#define P3G 2500
#define P3T 10
__global__ void __launch_bounds__(128) k_pass3(const float* __restrict__ w1,
    const float* __restrict__ w2, const float* __restrict__ w3){
    __shared__ __align__(16) float sw1[7*H1C];
    __shared__ __align__(16) float sw2[H1C*H2C];
    __shared__ __align__(16) float sw3[H2C*CC];
    __shared__ __align__(16) float sp1[2*H1C];
    __shared__ __align__(16) float sp2[2*H2C];
    __shared__ __align__(16) float h2sT[H2C*128];
    __shared__ float ss[CC], sq[CC];
    int t = threadIdx.x;
    if(t < 7*H1C) sw1[t]=w1[t];
    if(t < 2*H1C) sp1[t]=g_par1[t];
    if(t < 2*H2C) sp2[t]=g_par2[t];
    if(t < CC){ ss[t]=0.f; sq[t]=0.f; }
    for(int i=t;i<H1C*H2C;i+=128) sw2[i]=w2[i];
    for(int i=t;i<H2C*CC;i+=128) sw3[i]=w3[i];
    __syncthreads();

    const u64* scp1 = reinterpret_cast<const u64*>(sp1);
    const u64* shp1 = reinterpret_cast<const u64*>(sp1 + H1C);
    const u64* scp2 = reinterpret_cast<const u64*>(sp2);
    const u64* shp2 = reinterpret_cast<const u64*>(sp2 + H2C);

    int pl = t>>4;          // local point 0..7
    int c0 = (t&15)*4;      // channel group (stage B)

    float sreg[4], qreg[4];
    #pragma unroll
    for(int i=0;i<4;i++){ sreg[i]=0.f; qreg[i]=0.f; }

    int tile = blockIdx.x;
    float4 A = g_xc4[(tile*128 + t)*2];
    float4 B = g_xc4[(tile*128 + t)*2 + 1];

    #pragma unroll 1
    for(int it=0; it<P3T; it++){
        // ---- stage A: one thread per (point, neighbor) row; write transposed
        float x[7] = {A.x,A.y,A.z,A.w,B.x,B.y,B.z};
        u64 a1p[8]; lin1p(x, sw1, a1p);
        float h1[H1C];
        #pragma unroll
        for(int u=0;u<8;u++){
            u64 hv = gelu2(f2fma(a1p[u], scp1[u], shp1[u]));
            up2(hv, h1[2*u], h1[2*u+1]);
        }
        u64 a2p[16]; lin2p(h1, sw2, a2p);
        #pragma unroll
        for(int u=0;u<16;u++){
            u64 hv = gelu2(f2fma(a2p[u], scp2[u], shp2[u]));
            float lo, hi; up2(hv, lo, hi);
            h2sT[(2*u)*128 + t]   = lo;
            h2sT[(2*u+1)*128 + t] = hi;
        }

        // prefetch next tile's x (hidden behind stage B)
        int tilen = tile + P3G;
        if(it < P3T-1){
            A = g_xc4[(tilen*128 + t)*2];
            B = g_xc4[(tilen*128 + t)*2 + 1];
        }
        __syncthreads();

        // ---- stage B: thread = (point pl, channels c0..c0+3); q outer, 16 k inner
        u64 acc[8][4];
        #pragma unroll
        for(int a=0;a<8;a++)
            #pragma unroll
            for(int b=0;b<4;b++) acc[a][b]=0ull;
        const float* hbase = h2sT + pl*KN;
        #pragma unroll 4
        for(int q=0;q<H2C;q++){
            const float* hq = hbase + q*128;
            ulonglong2 hA = *reinterpret_cast<const ulonglong2*>(hq);
            ulonglong2 hB = *reinterpret_cast<const ulonglong2*>(hq+4);
            ulonglong2 hC = *reinterpret_cast<const ulonglong2*>(hq+8);
            ulonglong2 hD = *reinterpret_cast<const ulonglong2*>(hq+12);
            float4 wv = *reinterpret_cast<const float4*>(sw3 + q*CC + c0);
            u64 wp4[4] = {pk2(wv.x,wv.x), pk2(wv.y,wv.y), pk2(wv.z,wv.z), pk2(wv.w,wv.w)};
            u64 hk[8] = {hA.x,hA.y,hB.x,hB.y,hC.x,hC.y,hD.x,hD.y};
            #pragma unroll
            for(int kp=0;kp<8;kp++)
                #pragma unroll
                for(int ch=0;ch<4;ch++)
                    acc[kp][ch]=f2fma(hk[kp], wp4[ch], acc[kp][ch]);
        }
        float m[4] = {-3.4e38f,-3.4e38f,-3.4e38f,-3.4e38f};
        #pragma unroll
        for(int kp=0;kp<8;kp++)
            #pragma unroll
            for(int ch=0;ch<4;ch++){
                float lo, hi; up2(acc[kp][ch], lo, hi);
                m[ch] = fmaxf(m[ch], fmaxf(lo, hi));
            }
        int np = tile*8 + pl;
        float4 o; o.x=m[0]; o.y=m[1]; o.z=m[2]; o.w=m[3];
        *reinterpret_cast<float4*>(g_pooled + np*CC + c0) = o;
        #pragma unroll
        for(int ch=0;ch<4;ch++){ sreg[ch]+=m[ch]; qreg[ch]+=m[ch]*m[ch]; }

        tile = tilen;
        __syncthreads();   // h2sT reuse
    }

    #pragma unroll
    for(int i=0;i<4;i++){
        atomicAdd(&ss[c0+i], sreg[i]);
        atomicAdd(&sq[c0+i], qreg[i]);
    }
    __syncthreads();
    if(t < CC)        atomicAdd(&g_S3[t], (double)ss[t]);
    else if(t < 2*CC) atomicAdd(&g_Q3[t-CC], (double)sq[t-CC]);
}

// fused: compose bn_nbr+bn_post, build Weff and bias — one launch
__global__ void k_tail(const float* __restrict__ gn, const float* __restrict__ gp,
                       const float* __restrict__ bp, const float* __restrict__ wp){
    __shared__ float ssc[CC], ssh[CC];
    int t = threadIdx.x;
    if(t < CC){
        double m = g_S3[t]/(double)NP;
        double v = g_Q3[t]/(double)NP - m*m;
        double rs = rsqrt(v + BNEPS);
        double gnd = (double)gn[t];
        double vy = gnd*gnd*v*rs*rs;
        double rs2 = rsqrt(vy + BNEPS);
        double sc = gnd*rs*rs2*(double)gp[t];
        ssc[t]=(float)sc;
        ssh[t]=(float)((double)bp[t] - m*sc);
    }
    __syncthreads();
    for(int i=t;i<CC*HD;i+=256) g_Weff[i] = ssc[i>>8]*wp[i];
    float b=0.f;
    for(int c=0;c<CC;c++) b += ssh[c]*wp[c*HD+t];
    g_bias[t]=b;
}

// out[n][h] = pooled[n] . Weff[:,h] + bias[h]   (200000 x 64 x 256)
__global__ void __launch_bounds__(256) k_pass4(float* __restrict__ out){
    __shared__ __align__(16) float sW[CC*128];
    __shared__ __align__(16) float sPT[CC*68];
    __shared__ float sB[128];
    int t=threadIdx.x;
    int n0 = blockIdx.x*64;
    int hb = blockIdx.y*128;
    for(int i=t;i<CC*128;i+=256){ int c=i>>7, hh=i&127; sW[i]=g_Weff[c*HD+hb+hh]; }
    for(int i=t;i<64*CC;i+=256){ int c=i&63, pt=i>>6; sPT[c*68+pt]=g_pooled[(n0+pt)*CC + c]; }
    if(t<128) sB[t]=g_bias[hb+t];
    __syncthreads();
    int pi=t>>5, hj=t&31;
    u64 acc[4][4];     // [point-pair][hd]
    #pragma unroll
    for(int a=0;a<4;a++)
        #pragma unroll
        for(int b=0;b<4;b++) acc[a][b]=0ull;
    const float* pb = sPT + pi*8;
    #pragma unroll 4
    for(int c=0;c<CC;c++){
        ulonglong2 pA = *reinterpret_cast<const ulonglong2*>(pb + c*68);
        ulonglong2 pB = *reinterpret_cast<const ulonglong2*>(pb + c*68 + 4);
        float4 wv = *reinterpret_cast<const float4*>(sW + c*128 + hj*4);
        u64 w0=pk2(wv.x,wv.x), w1p=pk2(wv.y,wv.y), w2p=pk2(wv.z,wv.z), w3p=pk2(wv.w,wv.w);
        acc[0][0]=f2fma(pA.x,w0,acc[0][0]); acc[0][1]=f2fma(pA.x,w1p,acc[0][1]);
        acc[0][2]=f2fma(pA.x,w2p,acc[0][2]); acc[0][3]=f2fma(pA.x,w3p,acc[0][3]);
        acc[1][0]=f2fma(pA.y,w0,acc[1][0]); acc[1][1]=f2fma(pA.y,w1p,acc[1][1]);
        acc[1][2]=f2fma(pA.y,w2p,acc[1][2]); acc[1][3]=f2fma(pA.y,w3p,acc[1][3]);
        acc[2][0]=f2fma(pB.x,w0,acc[2][0]); acc[2][1]=f2fma(pB.x,w1p,acc[2][1]);
        acc[2][2]=f2fma(pB.x,w2p,acc[2][2]); acc[2][3]=f2fma(pB.x,w3p,acc[2][3]);
        acc[3][0]=f2fma(pB.y,w0,acc[3][0]); acc[3][1]=f2fma(pB.y,w1p,acc[3][1]);
        acc[3][2]=f2fma(pB.y,w2p,acc[3][2]); acc[3][3]=f2fma(pB.y,w3p,acc[3][3]);
    }
    float b0=sB[hj*4], b1=sB[hj*4+1], b2=sB[hj*4+2], b3=sB[hj*4+3];
    #pragma unroll
    for(int pq=0;pq<4;pq++){
        float e0,o0,e1,o1,e2,o2,e3,o3;
        up2(acc[pq][0],e0,o0); up2(acc[pq][1],e1,o1);
        up2(acc[pq][2],e2,o2); up2(acc[pq][3],e3,o3);
        int np = n0 + pi*8 + pq*2;
        float4 oe; oe.x=e0+b0; oe.y=e1+b1; oe.z=e2+b2; oe.w=e3+b3;
        float4 oo; oo.x=o0+b0; oo.y=o1+b1; oo.z=o2+b2; oo.w=o3+b3;
        *reinterpret_cast<float4*>(out + np*HD + hb + hj*4) = oe;
        *reinterpret_cast<float4*>(out + (np+1)*HD + hb + hj*4) = oo;
    }
}

extern "C" void kernel_launch(void* const* d_in, const int* in_sizes, int n_in,
                              void* d_out, int out_size){
    const float* p  = (const float*)d_in[0];
    const float* f  = (const float*)d_in[1];
    const int*   gi = (const int*)  d_in[2];
    const float* w1 = (const float*)d_in[3];
    const float* g1 = (const float*)d_in[4];
    const float* b1 = (const float*)d_in[5];
    const float* w2 = (const float*)d_in[6];
    const float* g2 = (const float*)d_in[7];
    const float* b2 = (const float*)d_in[8];
    const float* w3 = (const float*)d_in[9];
    const float* gn = (const float*)d_in[10];
    const float* bn = (const float*)d_in[11];
    const float* gp = (const float*)d_in[12];
    const float* bp = (const float*)d_in[13];
    const float* wp = (const float*)d_in[14];
    float* out = (float*)d_out;
    (void)in_sizes; (void)n_in; (void)out_size; (void)bn;

    k_init   <<<1, 256>>>();
    k_pass1m <<<(NP+255)/256, 256>>>(p, f, gi);
    k_stats1 <<<1, H1C>>>(w1, g1, b1);
    k_pass2m <<<625, 256>>>(w1);
    k_stats2 <<<1, H2C>>>(w2, g2, b2);
    k_pass3  <<<P3G, 128>>>(w1, w2, w3);
    k_tail   <<<1, 256>>>(gn, gp, bp, wp);
    k_pass4  <<<dim3(NP/64, 2), 256>>>(out);
}